// round 15
// baseline (speedup 1.0000x reference)
#include <cuda_runtime.h>
#include <cstdint>

#define BB    8
#define NN1   16384
#define NN2   4096
#define COUT  128
#define CHUNK 2048
#define NBIN  4096

typedef unsigned long long ull;

// Scratch (device globals; no allocation allowed)
__device__ float g_f0[(size_t)BB * COUT * NN2];      // layer0 output [B][128][N2]
__device__ float g_ft[(size_t)BB * NN2 * COUT];      // layer1 output transposed [B][N2][128]
__device__ float4 g_selw[(size_t)BB * NN1];          // per-query weights
__device__ int4   g_seli[(size_t)BB * NN1];          // per-query indices
__device__ int    g_hist[(size_t)BB * NBIN];         // per-batch bin histogram -> offsets
__device__ int    g_keys[(size_t)BB * NN1];          // per-query Morton cell key
__device__ int    g_perm[(size_t)BB * NN1];          // sorted query order

// ---------------------------------------------------------------------------
// packed f32x2 helpers (kNN distance evaluation only)
// ---------------------------------------------------------------------------
__device__ __forceinline__ void fma2(ull& d, ull a, ull b, ull c) {
    asm("fma.rn.f32x2 %0, %1, %2, %3;" : "=l"(d) : "l"(a), "l"(b), "l"(c));
}
__device__ __forceinline__ ull pack2(float lo, float hi) {
    ull r; asm("mov.b64 %0, {%1, %2};" : "=l"(r) : "f"(lo), "f"(hi)); return r;
}
__device__ __forceinline__ float2 unpack2(ull v) {
    float2 r; asm("mov.b64 {%0, %1}, %2;" : "=f"(r.x), "=f"(r.y) : "l"(v)); return r;
}
union F4U { float4 f; ull u[2]; };

// ---------------------------------------------------------------------------
// Fused 1x1 conv + BN + ReLU.  X:[B][CIN][N2]  W:[128][CIN]
// ---------------------------------------------------------------------------
template<int CIN, bool TRANS>
__global__ void __launch_bounds__(256)
conv_bn_relu_kernel(const float* __restrict__ X,
                    const float* __restrict__ W,
                    const float* __restrict__ bias,
                    const float* __restrict__ gamma,
                    const float* __restrict__ beta,
                    const float* __restrict__ mean,
                    const float* __restrict__ var,
                    float* __restrict__ out)
{
    __shared__ __align__(16) float Ws[32][132];
    __shared__ __align__(16) float Xs[32][68];

    const int t    = threadIdx.x;
    const int b    = blockIdx.y;
    const int n0   = blockIdx.x * 64;
    const int colb = (t & 7) * 8;
    const int rowb = (t >> 3) * 4;

    float acc[4][8];
#pragma unroll
    for (int i = 0; i < 4; i++)
#pragma unroll
        for (int j = 0; j < 8; j++) acc[i][j] = 0.f;

    const float* Xb = X + (size_t)b * CIN * NN2;

    for (int c0 = 0; c0 < CIN; c0 += 32) {
#pragma unroll
        for (int k = 0; k < 16; k++) {
            int idx = t + k * 256;
            int r = idx >> 5, c = idx & 31;
            Ws[c][r] = W[r * CIN + c0 + c];
        }
#pragma unroll
        for (int k = 0; k < 8; k++) {
            int idx = t + k * 256;
            int cc = idx >> 6, nn = idx & 63;
            Xs[cc][nn] = Xb[(size_t)(c0 + cc) * NN2 + n0 + nn];
        }
        __syncthreads();

#pragma unroll
        for (int cc = 0; cc < 32; cc++) {
            float4 xlo = *(const float4*)&Xs[cc][colb];
            float4 xhi = *(const float4*)&Xs[cc][colb + 4];
            float4 wv  = *(const float4*)&Ws[cc][rowb];
            float xr[8] = {xlo.x, xlo.y, xlo.z, xlo.w, xhi.x, xhi.y, xhi.z, xhi.w};
            float wr[4] = {wv.x, wv.y, wv.z, wv.w};
#pragma unroll
            for (int i = 0; i < 4; i++)
#pragma unroll
                for (int j = 0; j < 8; j++)
                    acc[i][j] = fmaf(wr[i], xr[j], acc[i][j]);
        }
        __syncthreads();
    }

    float val[4][8];
#pragma unroll
    for (int i = 0; i < 4; i++) {
        int r = rowb + i;
        float sc = gamma[r] * rsqrtf(var[r] + 1e-5f);
        float sh = fmaf(bias[r] - mean[r], sc, beta[r]);
#pragma unroll
        for (int j = 0; j < 8; j++)
            val[i][j] = fmaxf(fmaf(acc[i][j], sc, sh), 0.f);
    }

    if (!TRANS) {
#pragma unroll
        for (int i = 0; i < 4; i++) {
            float* o = &out[((size_t)b * COUT + rowb + i) * NN2 + n0 + colb];
            *(float4*)&o[0] = make_float4(val[i][0], val[i][1], val[i][2], val[i][3]);
            *(float4*)&o[4] = make_float4(val[i][4], val[i][5], val[i][6], val[i][7]);
        }
    } else {
#pragma unroll
        for (int j = 0; j < 8; j++) {
            float4 v = make_float4(val[0][j], val[1][j], val[2][j], val[3][j]);
            *(float4*)&out[((size_t)b * NN2 + n0 + colb + j) * COUT + rowb] = v;
        }
    }
}

// ---------------------------------------------------------------------------
// Query spatial sort: Morton key histogram -> prefix -> scatter (counting sort)
// ---------------------------------------------------------------------------
__device__ __forceinline__ int cellc(float v) {
    int c = __float2int_rd((v + 4.f) * 2.f);
    return min(15, max(0, c));
}
__device__ __forceinline__ int morton(int x, int y, int z) {
    int m = 0;
#pragma unroll
    for (int i = 0; i < 4; i++)
        m |= (((x >> i) & 1) << (3 * i)) |
             (((y >> i) & 1) << (3 * i + 1)) |
             (((z >> i) & 1) << (3 * i + 2));
    return m;
}

__global__ void __launch_bounds__(256)
hist_kernel(const float* __restrict__ p1, int* __restrict__ hist, int* __restrict__ keys)
{
    const int t = threadIdx.x;
    const int b = blockIdx.y;
    const int n = blockIdx.x * 256 + t;
    const float* pp = p1 + ((size_t)b * NN1 + n) * 3;
    int key = morton(cellc(pp[0]), cellc(pp[1]), cellc(pp[2]));
    keys[(size_t)b * NN1 + n] = key;
    atomicAdd(&hist[b * NBIN + key], 1);
}

__global__ void __launch_bounds__(1024)
scan_kernel(int* __restrict__ hist)   // grid = BB, block = 1024; 4 bins/thread
{
    __shared__ int ps[1024];
    const int b = blockIdx.x, t = threadIdx.x;
    int* h = hist + b * NBIN;
    int v0 = h[t * 4 + 0], v1 = h[t * 4 + 1], v2 = h[t * 4 + 2], v3 = h[t * 4 + 3];
    ps[t] = v0 + v1 + v2 + v3;
    __syncthreads();
    for (int off = 1; off < 1024; off <<= 1) {
        int x = 0;
        if (t >= off) x = ps[t - off];
        __syncthreads();
        if (t >= off) ps[t] += x;
        __syncthreads();
    }
    int excl = (t == 0) ? 0 : ps[t - 1];
    h[t * 4 + 0] = excl;
    h[t * 4 + 1] = excl + v0;
    h[t * 4 + 2] = excl + v0 + v1;
    h[t * 4 + 3] = excl + v0 + v1 + v2;
}

__global__ void __launch_bounds__(256)
scatter_kernel(const int* __restrict__ keys, int* __restrict__ hist, int* __restrict__ perm)
{
    const int t = threadIdx.x;
    const int b = blockIdx.y;
    const int n = blockIdx.x * 256 + t;
    int key = keys[(size_t)b * NN1 + n];
    int pos = atomicAdd(&hist[b * NBIN + key], 1);
    perm[(size_t)b * NN1 + pos] = n;
}

// ---------------------------------------------------------------------------
// branchless top-3 insert (ascending d0<=d1<=d2); correct even if s>=d2
// ---------------------------------------------------------------------------
__device__ __forceinline__ void ins3(float s, int id,
                                     float& d0, float& d1, float& d2,
                                     int& i0, int& i1, int& i2)
{
    bool c2 = s < d2, c1 = s < d1, c0 = s < d0;
    float nd2 = c1 ? d1 : (c2 ? s : d2);
    int   ni2 = c1 ? i1 : (c2 ? id : i2);
    float nd1 = c0 ? d0 : (c1 ? s : d1);
    int   ni1 = c0 ? i0 : (c1 ? id : i1);
    d0 = c0 ? s : d0;  i0 = c0 ? id : i0;
    d1 = nd1; i1 = ni1;
    d2 = nd2; i2 = ni2;
}

// ---------------------------------------------------------------------------
// 3-NN selection, 2 queries/thread, queries taken in SPATIALLY SORTED order
// (warp-coherent insert events -> near-uniform slow-path branch).
// Results written to ORIGINAL query slots; math identical to unsorted version.
// ---------------------------------------------------------------------------
__global__ void __launch_bounds__(256)
knn_select_kernel(const float* __restrict__ p1,
                  const float* __restrict__ p2,
                  const int* __restrict__ perm,
                  float4* __restrict__ selw,
                  int4*   __restrict__ seli)
{
    __shared__ __align__(16) float sx[CHUNK];
    __shared__ __align__(16) float sy[CHUNK];
    __shared__ __align__(16) float sz[CHUNK];
    __shared__ __align__(16) float sw[CHUNK];

    const int t = threadIdx.x;
    const int b = blockIdx.y;
    const int n0 = blockIdx.x * 512;
    const int qA = perm[(size_t)b * NN1 + n0 + t];
    const int qB = perm[(size_t)b * NN1 + n0 + 256 + t];

    const float* ppA = p1 + ((size_t)b * NN1 + qA) * 3;
    const float* ppB = p1 + ((size_t)b * NN1 + qB) * 3;
    const float axp = ppA[0], ayp = ppA[1], azp = ppA[2];
    const float bxp = ppB[0], byp = ppB[1], bzp = ppB[2];

    const ull MXA = pack2(-2.f * axp, -2.f * axp);
    const ull MYA = pack2(-2.f * ayp, -2.f * ayp);
    const ull MZA = pack2(-2.f * azp, -2.f * azp);
    const ull MXB = pack2(-2.f * bxp, -2.f * bxp);
    const ull MYB = pack2(-2.f * byp, -2.f * byp);
    const ull MZB = pack2(-2.f * bzp, -2.f * bzp);
    const float cA = axp * axp + ayp * ayp + azp * azp;
    const float cB = bxp * bxp + byp * byp + bzp * bzp;

    const float INF = __int_as_float(0x7f800000);
    float dA0 = INF, dA1 = INF, dA2 = INF;
    int   iA0 = 0,   iA1 = 0,   iA2 = 0;
    float dB0 = INF, dB1 = INF, dB2 = INF;
    int   iB0 = 0,   iB1 = 0,   iB2 = 0;

    const float* p2b = p2 + (size_t)b * NN2 * 3;

    for (int base = 0; base < NN2; base += CHUNK) {
        for (int k = t; k < CHUNK; k += 256) {
            const float* q = p2b + (size_t)(base + k) * 3;
            float x = q[0], y = q[1], z = q[2];
            sx[k] = x; sy[k] = y; sz[k] = z;
            sw[k] = fmaf(x, x, fmaf(y, y, z * z));
        }
        __syncthreads();

#pragma unroll 2
        for (int k = 0; k < CHUNK; k += 4) {
            F4U xq, yq, zq, wq;
            xq.f = *(const float4*)&sx[k];
            yq.f = *(const float4*)&sy[k];
            zq.f = *(const float4*)&sz[k];
            wq.f = *(const float4*)&sw[k];

            ull a01 = wq.u[0], a23 = wq.u[1];
            fma2(a01, xq.u[0], MXA, a01);
            fma2(a01, yq.u[0], MYA, a01);
            fma2(a01, zq.u[0], MZA, a01);
            fma2(a23, xq.u[1], MXA, a23);
            fma2(a23, yq.u[1], MYA, a23);
            fma2(a23, zq.u[1], MZA, a23);
            ull b01 = wq.u[0], b23 = wq.u[1];
            fma2(b01, xq.u[0], MXB, b01);
            fma2(b01, yq.u[0], MYB, b01);
            fma2(b01, zq.u[0], MZB, b01);
            fma2(b23, xq.u[1], MXB, b23);
            fma2(b23, yq.u[1], MYB, b23);
            fma2(b23, zq.u[1], MZB, b23);

            float2 aa = unpack2(a01);
            float2 ac = unpack2(a23);
            float2 ba = unpack2(b01);
            float2 bc = unpack2(b23);
            float mA = fminf(fminf(aa.x, aa.y), fminf(ac.x, ac.y));
            float mB = fminf(fminf(ba.x, ba.y), fminf(bc.x, bc.y));
            int id = base + k;
            if (mA < dA2) {
                ins3(aa.x, id + 0, dA0, dA1, dA2, iA0, iA1, iA2);
                ins3(aa.y, id + 1, dA0, dA1, dA2, iA0, iA1, iA2);
                ins3(ac.x, id + 2, dA0, dA1, dA2, iA0, iA1, iA2);
                ins3(ac.y, id + 3, dA0, dA1, dA2, iA0, iA1, iA2);
            }
            if (mB < dB2) {
                ins3(ba.x, id + 0, dB0, dB1, dB2, iB0, iB1, iB2);
                ins3(ba.y, id + 1, dB0, dB1, dB2, iB0, iB1, iB2);
                ins3(bc.x, id + 2, dB0, dB1, dB2, iB0, iB1, iB2);
                ins3(bc.y, id + 3, dB0, dB1, dB2, iB0, iB1, iB2);
            }
        }
        __syncthreads();
    }

    {
        float r0 = 1.f / (dA0 + cA + 1e-8f);
        float r1 = 1.f / (dA1 + cA + 1e-8f);
        float r2 = 1.f / (dA2 + cA + 1e-8f);
        float inv = 1.f / (r0 + r1 + r2);
        size_t qi = (size_t)b * NN1 + qA;
        selw[qi] = make_float4(r0 * inv, r1 * inv, r2 * inv, 0.f);
        seli[qi] = make_int4(iA0, iA1, iA2, 0);
    }
    {
        float r0 = 1.f / (dB0 + cB + 1e-8f);
        float r1 = 1.f / (dB1 + cB + 1e-8f);
        float r2 = 1.f / (dB2 + cB + 1e-8f);
        float inv = 1.f / (r0 + r1 + r2);
        size_t qi = (size_t)b * NN1 + qB;
        selw[qi] = make_float4(r0 * inv, r1 * inv, r2 * inv, 0.f);
        seli[qi] = make_int4(iB0, iB1, iB2, 0);
    }
}

// ---------------------------------------------------------------------------
// Gather + weighted sum, warp-per-query (coalesced 512B row reads).
// ---------------------------------------------------------------------------
__global__ void __launch_bounds__(256)
gather_kernel(const float* __restrict__ ft,      // [B][N2][128]
              const float4* __restrict__ selw,
              const int4*   __restrict__ seli,
              float* __restrict__ out)           // [B][128][N1]
{
    __shared__ float res[32][133];

    const int t  = threadIdx.x;
    const int b  = blockIdx.y;
    const int n0 = blockIdx.x * 32;
    const int w  = t >> 5, l = t & 31;

    const float* ftb = ft + (size_t)b * NN2 * COUT;

#pragma unroll
    for (int qq = 0; qq < 4; qq++) {
        int q = w * 4 + qq;
        size_t qi = (size_t)b * NN1 + n0 + q;
        float4 wt = selw[qi];
        int4   id = seli[qi];
        const float4* f0 = (const float4*)(ftb + (size_t)id.x * COUT);
        const float4* f1 = (const float4*)(ftb + (size_t)id.y * COUT);
        const float4* f2 = (const float4*)(ftb + (size_t)id.z * COUT);
        float4 a = f0[l], c = f1[l], e = f2[l];
        res[q][l * 4 + 0] = wt.x * a.x + wt.y * c.x + wt.z * e.x;
        res[q][l * 4 + 1] = wt.x * a.y + wt.y * c.y + wt.z * e.y;
        res[q][l * 4 + 2] = wt.x * a.z + wt.y * c.z + wt.z * e.z;
        res[q][l * 4 + 3] = wt.x * a.w + wt.y * c.w + wt.z * e.w;
    }
    __syncthreads();

#pragma unroll
    for (int it = 0; it < 16; it++) {
        int idx = t + it * 256;
        int c = idx >> 5, nn = idx & 31;
        out[((size_t)b * COUT + c) * NN1 + n0 + nn] = res[nn][c];
    }
}

// ---------------------------------------------------------------------------
extern "C" void kernel_launch(void* const* d_in, const int* in_sizes, int n_in,
                              void* d_out, int out_size)
{
    const float* p1 = (const float*)d_in[0];
    const float* p2 = (const float*)d_in[1];
    const float* f2 = (const float*)d_in[2];
    const float* W0 = (const float*)d_in[3];
    const float* b0 = (const float*)d_in[4];
    const float* g0 = (const float*)d_in[5];
    const float* be0 = (const float*)d_in[6];
    const float* m0 = (const float*)d_in[7];
    const float* v0 = (const float*)d_in[8];
    const float* W1 = (const float*)d_in[9];
    const float* b1 = (const float*)d_in[10];
    const float* g1 = (const float*)d_in[11];
    const float* be1 = (const float*)d_in[12];
    const float* m1 = (const float*)d_in[13];
    const float* v1 = (const float*)d_in[14];

    float*  f0p = nullptr;
    float*  ftp = nullptr;
    float4* swp = nullptr;
    int4*   sip = nullptr;
    int*    hp  = nullptr;
    int*    kp  = nullptr;
    int*    pp  = nullptr;
    cudaGetSymbolAddress((void**)&f0p, g_f0);
    cudaGetSymbolAddress((void**)&ftp, g_ft);
    cudaGetSymbolAddress((void**)&swp, g_selw);
    cudaGetSymbolAddress((void**)&sip, g_seli);
    cudaGetSymbolAddress((void**)&hp,  g_hist);
    cudaGetSymbolAddress((void**)&kp,  g_keys);
    cudaGetSymbolAddress((void**)&pp,  g_perm);

    // Fork a side stream for the kNN pipeline (independent of the convs).
    cudaStream_t s2;
    cudaStreamCreateWithFlags(&s2, cudaStreamNonBlocking);
    cudaEvent_t evFork, evJoin;
    cudaEventCreateWithFlags(&evFork, cudaEventDisableTiming);
    cudaEventCreateWithFlags(&evJoin, cudaEventDisableTiming);

    cudaEventRecord(evFork, 0);
    cudaStreamWaitEvent(s2, evFork, 0);

    // --- side stream: spatial counting sort of queries, then kNN selection
    cudaMemsetAsync(hp, 0, (size_t)BB * NBIN * sizeof(int), s2);
    dim3 qgrid(NN1 / 256, BB);
    hist_kernel<<<qgrid, 256, 0, s2>>>(p1, hp, kp);
    scan_kernel<<<BB, 1024, 0, s2>>>(hp);
    scatter_kernel<<<qgrid, 256, 0, s2>>>(kp, hp, pp);
    dim3 kgrid(NN1 / 512, BB);
    knn_select_kernel<<<kgrid, 256, 0, s2>>>(p1, p2, pp, swp, sip);

    // --- main stream: conv chain
    dim3 ggrid(NN2 / 64, BB);
    conv_bn_relu_kernel<256, false><<<ggrid, 256>>>(f2, W0, b0, g0, be0, m0, v0, f0p);
    conv_bn_relu_kernel<128, true ><<<ggrid, 256>>>(f0p, W1, b1, g1, be1, m1, v1, ftp);

    cudaEventRecord(evJoin, s2);
    cudaStreamWaitEvent(0, evJoin, 0);

    dim3 grgrid(NN1 / 32, BB);
    gather_kernel<<<grgrid, 256>>>(ftp, swp, sip, (float*)d_out);
}